// round 1
// baseline (speedup 1.0000x reference)
#include <cuda_runtime.h>
#include <math.h>

#define B_  4
#define HWC 4096    // 64*64
#define HWF 16384   // 128*128

// ---------------- scratch (static device globals; no runtime allocation) ----------------
__device__ float g_cm0[B_*3*HWC];        // coarse_matches0 (warp x,y, 0)
__device__ float g_warped1c[B_*64*HWC];
__device__ float g_xin[B_*130*HWC];
__device__ float g_cbuf0[B_*256*HWC];
__device__ float g_cbuf1[B_*256*HWC];
__device__ float g_cm[B_*3*HWC];         // coarse_matches (final)
__device__ float g_up[B_*3*HWF];
__device__ float g_warped1f[B_*24*HWF];
__device__ float g_yin[B_*50*HWF];
__device__ float g_fbuf0[B_*64*HWF];
__device__ float g_fbuf1[B_*64*HWF];
__device__ float g_bnscale[256];
__device__ float g_bnshift[256];

// ---------------- fused correlation + softmax + expected-position ("attention") ----------
// block = (h row, batch). 64 queries/row, 4096 keys, D=64, V = analytic pos grid.
// threads: 256 = 16 query-groups(4q) x 16 key-lanes(4k). Online softmax per thread,
// final merge across the 16 key-lanes via smem log-sum-exp combine.
__global__ void attention_kernel(const float* __restrict__ f0, const float* __restrict__ f1) {
    int b = blockIdx.y, h = blockIdx.x;
    int tid = threadIdx.x;
    __shared__ float q_s[64][65];
    __shared__ float k_s[64][65];
    const float* f0b = f0 + (size_t)b*64*HWC;
    const float* f1b = f1 + (size_t)b*64*HWC;
    for (int idx = tid; idx < 4096; idx += 256) {
        int c = idx >> 6, q = idx & 63;
        q_s[c][q] = f0b[c*HWC + h*64 + q];
    }
    int tq = tid >> 4, tk = tid & 15;
    float m[4], ss[4], px[4], py[4];
#pragma unroll
    for (int i = 0; i < 4; i++) { m[i] = -1e30f; ss[i] = 0.f; px[i] = 0.f; py[i] = 0.f; }

    for (int t = 0; t < 64; ++t) {
        __syncthreads();
        for (int idx = tid; idx < 4096; idx += 256) {
            int c = idx >> 6, j = idx & 63;
            k_s[c][j] = f1b[c*HWC + t*64 + j];
        }
        __syncthreads();
        float sc[4][4];
#pragma unroll
        for (int i = 0; i < 4; i++)
#pragma unroll
            for (int j = 0; j < 4; j++) sc[i][j] = 0.f;
#pragma unroll 8
        for (int c = 0; c < 64; ++c) {
            float qf[4], kf[4];
#pragma unroll
            for (int i = 0; i < 4; i++) qf[i] = q_s[c][tq*4+i];
#pragma unroll
            for (int j = 0; j < 4; j++) kf[j] = k_s[c][tk*4+j];
#pragma unroll
            for (int i = 0; i < 4; i++)
#pragma unroll
                for (int j = 0; j < 4; j++) sc[i][j] = fmaf(qf[i], kf[j], sc[i][j]);
        }
#pragma unroll
        for (int i = 0; i < 4; i++) {
            float mt = m[i];
#pragma unroll
            for (int j = 0; j < 4; j++) mt = fmaxf(mt, sc[i][j]*0.125f);
            float f = __expf(m[i] - mt);
            float es = 0.f, ex = 0.f, ey = 0.f;
#pragma unroll
            for (int j = 0; j < 4; j++) {
                int jj = t*64 + tk*4 + j;
                float e  = __expf(sc[i][j]*0.125f - mt);
                float gx = (float)(2*(jj & 63) + 1) * (1.0f/64.0f) - 1.0f;
                float gy = (float)(2*(jj >> 6) + 1) * (1.0f/64.0f) - 1.0f;
                es += e; ex += e*gx; ey += e*gy;
            }
            ss[i] = ss[i]*f + es; px[i] = px[i]*f + ex; py[i] = py[i]*f + ey; m[i] = mt;
        }
    }
    __syncthreads();
    float* red = &k_s[0][0];   // reuse 4160 floats >= 4096
#pragma unroll
    for (int i = 0; i < 4; i++) {
        int q = tq*4 + i;
        red[       q*16+tk] = m[i];
        red[1024 + q*16+tk] = ss[i];
        red[2048 + q*16+tk] = px[i];
        red[3072 + q*16+tk] = py[i];
    }
    __syncthreads();
    if (tid < 64) {
        int q = tid;
        float M = -1e30f;
        for (int t2 = 0; t2 < 16; t2++) M = fmaxf(M, red[q*16+t2]);
        float S = 0.f, X = 0.f, Y = 0.f;
        for (int t2 = 0; t2 < 16; t2++) {
            float f = __expf(red[q*16+t2] - M);
            S += red[1024 + q*16+t2]*f;
            X += red[2048 + q*16+t2]*f;
            Y += red[3072 + q*16+t2]*f;
        }
        int p = h*64 + q;
        g_cm0[(b*3+0)*HWC + p] = X / S;
        g_cm0[(b*3+1)*HWC + p] = Y / S;
        g_cm0[(b*3+2)*HWC + p] = 0.0f;
    }
}

// ---------------- bilinear grid-sample (zero padding via valid mask, matches reference) --
__global__ void gridsample_kernel(const float* __restrict__ img, const float* __restrict__ cm,
                                  float* __restrict__ out, int C, int H, int W) {
    int idx = blockIdx.x*256 + threadIdx.x;
    int HW = H*W;
    int total = B_*C*HW;
    if (idx >= total) return;
    int p = idx % HW; int c = (idx / HW) % C; int b = idx / (HW*C);
    float gx = cm[(b*3+0)*HW + p];
    float gy = cm[(b*3+1)*HW + p];
    float x = (gx + 1.0f)*(W*0.5f) - 0.5f;
    float y = (gy + 1.0f)*(H*0.5f) - 0.5f;
    float x0f = floorf(x), y0f = floorf(y);
    float wx = x - x0f, wy = y - y0f;
    int x0 = (int)x0f, y0 = (int)y0f;
    const float* im = img + (size_t)(b*C + c)*HW;
    float v[4];
#pragma unroll
    for (int iy = 0; iy < 2; iy++)
#pragma unroll
        for (int ix = 0; ix < 2; ix++) {
            int xi = x0 + ix, yi = y0 + iy;
            bool valid = (xi >= 0 && xi < W && yi >= 0 && yi < H);
            int xc = min(max(xi, 0), W-1), yc = min(max(yi, 0), H-1);
            v[iy*2+ix] = valid ? im[yc*W + xc] : 0.0f;
        }
    out[idx] = v[0]*(1-wx)*(1-wy) + v[1]*wx*(1-wy) + v[2]*(1-wx)*wy + v[3]*wx*wy;
}

// ---------------- channel concat builders ----------------
__global__ void concat_c_kernel(const float* __restrict__ f0c) {
    int idx = blockIdx.x*256 + threadIdx.x;
    if (idx >= B_*130*HWC) return;
    int p = idx % HWC; int c = (idx / HWC) % 130; int b = idx / (HWC*130);
    float v;
    if (c < 64)       v = f0c[(b*64 + c)*HWC + p];
    else if (c < 128) v = g_warped1c[(b*64 + (c-64))*HWC + p];
    else              v = g_cm0[(b*3 + (c-128))*HWC + p];
    g_xin[idx] = v;
}

__global__ void concat_f_kernel(const float* __restrict__ f0f) {
    int idx = blockIdx.x*256 + threadIdx.x;
    if (idx >= B_*50*HWF) return;
    int p = idx % HWF; int c = (idx / HWF) % 50; int b = idx / (HWF*50);
    float v;
    if (c < 24)      v = f0f[(b*24 + c)*HWF + p];
    else if (c < 48) v = g_warped1f[(b*24 + (c-24))*HWF + p];
    else             v = g_up[(b*3 + (c-48))*HWF + p];
    g_yin[idx] = v;
}

// ---------------- direct 3x3 conv, SAME, 64oc x 8x8px tile, 4oc x 4px register tile -----
// input BN(scale,shift)+relu optionally fused on load (previous layer's batchnorm).
__global__ void conv3x3_kernel(const float* __restrict__ in, const float* __restrict__ wgt,
                               float* __restrict__ out,
                               int CIN, int COUT, int H, int W, int applyBn) {
    int b = blockIdx.z;
    int oc0 = blockIdx.y * 64;
    int tilesW = W >> 3;
    int th0 = (blockIdx.x / tilesW) * 8;
    int tw0 = (blockIdx.x % tilesW) * 8;
    int tid = threadIdx.x;

    __shared__ float s_in[8][10][11];
    __shared__ float4 s_w4[8][9][16];
    float* s_wf = (float*)s_w4;

    int txoc = tid & 15;
    int tpx  = tid >> 4;
    int hl   = tpx >> 1;
    int wl0  = (tpx & 1) * 4;

    float acc[4][4];
#pragma unroll
    for (int i = 0; i < 4; i++)
#pragma unroll
        for (int j = 0; j < 4; j++) acc[i][j] = 0.f;

    int nChunks = (CIN + 7) >> 3;
    for (int ch = 0; ch < nChunks; ++ch) {
        int ic0 = ch * 8;
        __syncthreads();
        // fill input tile 8ic x 10x10 (+BN/relu)
        for (int idx = tid; idx < 800; idx += 256) {
            int ic = idx / 100; int r = (idx % 100) / 10; int cpos = idx % 10;
            int gh = th0 + r - 1, gw = tw0 + cpos - 1;
            int icg = ic0 + ic;
            float v = 0.0f;
            if (icg < CIN && gh >= 0 && gh < H && gw >= 0 && gw < W) {
                v = in[((size_t)(b*CIN + icg)*H + gh)*W + gw];
                if (applyBn) v = fmaxf(fmaf(v, g_bnscale[icg], g_bnshift[icg]), 0.0f);
            }
            s_in[ic][r][cpos] = v;
        }
        // fill weights 8ic x 9k x 64oc (oc fastest for vector read)
        for (int idx = tid; idx < 8*9*64; idx += 256) {
            int ic = idx / (9*64); int k = (idx / 64) % 9; int oc = idx % 64;
            int icg = ic0 + ic;
            float v = (icg < CIN) ? wgt[((size_t)(oc0+oc)*CIN + icg)*9 + k] : 0.0f;
            s_wf[(ic*9 + k)*64 + oc] = v;
        }
        __syncthreads();
#pragma unroll 4
        for (int ic = 0; ic < 8; ++ic) {
#pragma unroll
            for (int k = 0; k < 9; ++k) {
                int kh = k / 3, kw = k % 3;
                float4 wv = s_w4[ic][k][txoc];
                float wvv[4] = {wv.x, wv.y, wv.z, wv.w};
                float iv[4];
#pragma unroll
                for (int j = 0; j < 4; j++) iv[j] = s_in[ic][hl+kh][wl0+kw+j];
#pragma unroll
                for (int i = 0; i < 4; i++)
#pragma unroll
                    for (int j = 0; j < 4; j++)
                        acc[i][j] = fmaf(wvv[i], iv[j], acc[i][j]);
            }
        }
    }
#pragma unroll
    for (int i = 0; i < 4; i++) {
        int oc = oc0 + txoc*4 + i;
#pragma unroll
        for (int j = 0; j < 4; j++)
            out[((size_t)(b*COUT + oc)*H + th0+hl)*W + tw0+wl0+j] = acc[i][j];
    }
}

// ---------------- per-channel batch stats -> scale/shift ----------------
__global__ void bnstats_kernel(const float* __restrict__ in, int C, int HW) {
    int c = blockIdx.x;
    int tid = threadIdx.x;
    float s = 0.f, s2 = 0.f;
    for (int b = 0; b < B_; ++b) {
        const float* p = in + (size_t)(b*C + c)*HW;
        for (int i = tid; i < HW; i += 256) { float v = p[i]; s += v; s2 += v*v; }
    }
    __shared__ float sh[256], sh2[256];
    sh[tid] = s; sh2[tid] = s2;
    __syncthreads();
    for (int o = 128; o > 0; o >>= 1) {
        if (tid < o) { sh[tid] += sh[tid+o]; sh2[tid] += sh2[tid+o]; }
        __syncthreads();
    }
    if (tid == 0) {
        float n = (float)(B_*HW);
        float mean = sh[0] / n;
        float var  = sh2[0] / n - mean*mean;
        float sc = rsqrtf(var + 1e-5f);
        g_bnscale[c] = sc;
        g_bnshift[c] = -mean * sc;
    }
}

// ---------------- 1x1 conv head: out = base + bias + W * relu(bn(in)) ----------------
__global__ void conv1x1_kernel(const float* __restrict__ inbuf, const float* __restrict__ wgt,
                               const float* __restrict__ bias, const float* __restrict__ base,
                               float* __restrict__ dout, float* __restrict__ dup,
                               int CIN, int HW) {
    __shared__ float s_w[3*256], s_sc[256], s_sh[256];
    int tid = threadIdx.x;
    for (int i = tid; i < 3*CIN; i += 256) s_w[i] = wgt[i];
    for (int i = tid; i < CIN; i += 256) { s_sc[i] = g_bnscale[i]; s_sh[i] = g_bnshift[i]; }
    __syncthreads();
    int idx = blockIdx.x*256 + tid;
    int p = idx % HW, b = idx / HW;
    float a0 = bias[0], a1 = bias[1], a2 = bias[2];
    const float* ip = inbuf + (size_t)b*CIN*HW + p;
    for (int ic = 0; ic < CIN; ++ic) {
        float v = ip[(size_t)ic*HW];
        v = fmaxf(fmaf(v, s_sc[ic], s_sh[ic]), 0.0f);
        a0 = fmaf(v, s_w[ic],        a0);
        a1 = fmaf(v, s_w[CIN+ic],    a1);
        a2 = fmaf(v, s_w[2*CIN+ic],  a2);
    }
    float r0 = base[(b*3+0)*HW + p] + a0;
    float r1 = base[(b*3+1)*HW + p] + a1;
    float r2 = base[(b*3+2)*HW + p] + a2;
    dout[(b*3+0)*HW + p] = r0;
    dout[(b*3+1)*HW + p] = r1;
    dout[(b*3+2)*HW + p] = r2;
    if (dup) {
        dup[(b*3+0)*HW + p] = r0;
        dup[(b*3+1)*HW + p] = r1;
        dup[(b*3+2)*HW + p] = r2;
    }
}

// ---------------- 2x bilinear upsample (half-pixel centers, edge clamp == jax renorm) ----
__global__ void upsample_kernel(const float* __restrict__ src3, float* __restrict__ dst3) {
    int idx = blockIdx.x*256 + threadIdx.x;
    if (idx >= B_*3*HWF) return;
    int p = idx % HWF; int c = (idx / HWF) % 3; int b = idx / (HWF*3);
    int wo = p & 127, ho = p >> 7;
    float sx = wo*0.5f - 0.25f, sy = ho*0.5f - 0.25f;
    float x0f = floorf(sx), y0f = floorf(sy);
    float wx = sx - x0f, wy = sy - y0f;
    int x0 = (int)x0f, y0 = (int)y0f;
    int x0c = min(max(x0, 0), 63),   x1c = min(max(x0+1, 0), 63);
    int y0c = min(max(y0, 0), 63),   y1c = min(max(y0+1, 0), 63);
    const float* s = src3 + (size_t)(b*3 + c)*HWC;
    float v = s[y0c*64+x0c]*(1-wx)*(1-wy) + s[y0c*64+x1c]*wx*(1-wy)
            + s[y1c*64+x0c]*(1-wx)*wy     + s[y1c*64+x1c]*wx*wy;
    dst3[idx] = v;
}

// ---------------- host driver (graph-capturable: kernel launches only) ----------------
extern "C" void kernel_launch(void* const* d_in, const int* in_sizes, int n_in,
                              void* d_out, int out_size) {
    const float* f0c = (const float*)d_in[0];
    const float* f1c = (const float*)d_in[1];
    const float* f0f = (const float*)d_in[2];
    const float* f1f = (const float*)d_in[3];
    const float* cw1 = (const float*)d_in[4];
    const float* cw2 = (const float*)d_in[5];
    const float* cw3 = (const float*)d_in[6];
    const float* cw4 = (const float*)d_in[7];
    const float* cw5 = (const float*)d_in[8];
    const float* cb5 = (const float*)d_in[9];
    const float* fw1 = (const float*)d_in[10];
    const float* fw2 = (const float*)d_in[11];
    const float* fw3 = (const float*)d_in[12];
    const float* fw4 = (const float*)d_in[13];
    const float* fw5 = (const float*)d_in[14];
    const float* fb5 = (const float*)d_in[15];

    float *p_cm0, *p_w1c, *p_xin, *p_c0, *p_c1, *p_cm, *p_up, *p_w1f, *p_yin, *p_f0, *p_f1;
    cudaGetSymbolAddress((void**)&p_cm0, g_cm0);
    cudaGetSymbolAddress((void**)&p_w1c, g_warped1c);
    cudaGetSymbolAddress((void**)&p_xin, g_xin);
    cudaGetSymbolAddress((void**)&p_c0,  g_cbuf0);
    cudaGetSymbolAddress((void**)&p_c1,  g_cbuf1);
    cudaGetSymbolAddress((void**)&p_cm,  g_cm);
    cudaGetSymbolAddress((void**)&p_up,  g_up);
    cudaGetSymbolAddress((void**)&p_w1f, g_warped1f);
    cudaGetSymbolAddress((void**)&p_yin, g_yin);
    cudaGetSymbolAddress((void**)&p_f0,  g_fbuf0);
    cudaGetSymbolAddress((void**)&p_f1,  g_fbuf1);

    // coarse path
    attention_kernel<<<dim3(64, B_), 256>>>(f0c, f1c);
    gridsample_kernel<<<(B_*64*HWC)/256, 256>>>(f1c, p_cm0, p_w1c, 64, 64, 64);
    concat_c_kernel<<<(B_*130*HWC + 255)/256, 256>>>(f0c);
    conv3x3_kernel<<<dim3(64, 4, B_), 256>>>(p_xin, cw1, p_c0, 130, 256, 64, 64, 0);
    bnstats_kernel<<<256, 256>>>(p_c0, 256, HWC);
    conv3x3_kernel<<<dim3(64, 4, B_), 256>>>(p_c0, cw2, p_c1, 256, 256, 64, 64, 1);
    bnstats_kernel<<<256, 256>>>(p_c1, 256, HWC);
    conv3x3_kernel<<<dim3(64, 4, B_), 256>>>(p_c1, cw3, p_c0, 256, 256, 64, 64, 1);
    bnstats_kernel<<<256, 256>>>(p_c0, 256, HWC);
    conv3x3_kernel<<<dim3(64, 4, B_), 256>>>(p_c0, cw4, p_c1, 256, 256, 64, 64, 1);
    bnstats_kernel<<<256, 256>>>(p_c1, 256, HWC);
    conv1x1_kernel<<<(B_*HWC)/256, 256>>>(p_c1, cw5, cb5, p_cm0, (float*)d_out, p_cm, 256, HWC);

    // fine path
    upsample_kernel<<<(B_*3*HWF)/256, 256>>>(p_cm, p_up);
    gridsample_kernel<<<(B_*24*HWF)/256, 256>>>(f1f, p_up, p_w1f, 24, 128, 128);
    concat_f_kernel<<<(B_*50*HWF + 255)/256, 256>>>(f0f);
    conv3x3_kernel<<<dim3(256, 1, B_), 256>>>(p_yin, fw1, p_f0, 50, 64, 128, 128, 0);
    bnstats_kernel<<<64, 256>>>(p_f0, 64, HWF);
    conv3x3_kernel<<<dim3(256, 1, B_), 256>>>(p_f0, fw2, p_f1, 64, 64, 128, 128, 1);
    bnstats_kernel<<<64, 256>>>(p_f1, 64, HWF);
    conv3x3_kernel<<<dim3(256, 1, B_), 256>>>(p_f1, fw3, p_f0, 64, 64, 128, 128, 1);
    bnstats_kernel<<<64, 256>>>(p_f0, 64, HWF);
    conv3x3_kernel<<<dim3(256, 1, B_), 256>>>(p_f0, fw4, p_f1, 64, 64, 128, 128, 1);
    bnstats_kernel<<<64, 256>>>(p_f1, 64, HWF);
    conv1x1_kernel<<<(B_*HWF)/256, 256>>>(p_f1, fw5, fb5, p_up,
                                          (float*)d_out + B_*3*HWC, (float*)0, 64, HWF);
}

// round 2
// speedup vs baseline: 1.5239x; 1.5239x over previous
#include <cuda_runtime.h>
#include <math.h>

#define B_  4
#define HWC 4096    // 64*64
#define HWF 16384   // 128*128

typedef unsigned long long ull;

__device__ __forceinline__ ull pk2(float a, float b) {
    ull r; asm("mov.b64 %0, {%1,%2};" : "=l"(r) : "f"(a), "f"(b)); return r;
}
__device__ __forceinline__ ull fma2(ull a, ull b, ull c) {
    ull d; asm("fma.rn.f32x2 %0, %1, %2, %3;" : "=l"(d) : "l"(a), "l"(b), "l"(c)); return d;
}
__device__ __forceinline__ void unpk2(ull v, float& lo, float& hi) {
    asm("mov.b64 {%0,%1}, %2;" : "=f"(lo), "=f"(hi) : "l"(v));
}

// ---------------- scratch (static device globals; no runtime allocation) ----------------
__device__ float g_cm0[B_*3*HWC];        // coarse_matches0 (warp x,y, 0)
__device__ float g_warped1c[B_*64*HWC];
__device__ float g_xin[B_*130*HWC];
__device__ float g_cbuf0[B_*256*HWC];
__device__ float g_cbuf1[B_*256*HWC];
__device__ float g_cm[B_*3*HWC];         // coarse_matches (final)
__device__ float g_up[B_*3*HWF];
__device__ float g_warped1f[B_*24*HWF];
__device__ float g_yin[B_*50*HWF];
__device__ float g_fbuf0[B_*64*HWF];
__device__ float g_fbuf1[B_*64*HWF];
__device__ float g_bnscale[256];
__device__ float g_bnshift[256];

// ---------------- fused correlation + softmax + expected-position ("attention") ----------
// block = (h row, batch). 64 queries/row, 4096 keys, D=64, V = analytic pos grid.
// 256 threads = 16 query-groups(4q) x 16 key-lanes(4k). QK inner product in packed f32x2.
__global__ void attention_kernel(const float* __restrict__ f0, const float* __restrict__ f1) {
    int b = blockIdx.y, h = blockIdx.x;
    int tid = threadIdx.x;
    __shared__ __align__(16) float q_s[64][66];
    __shared__ __align__(16) float k_s[64][66];
    const float* f0b = f0 + (size_t)b*64*HWC;
    const float* f1b = f1 + (size_t)b*64*HWC;
    for (int idx = tid; idx < 4096; idx += 256) {
        int c = idx >> 6, q = idx & 63;
        q_s[c][q] = f0b[c*HWC + h*64 + q];
    }
    int tq = tid >> 4, tk = tid & 15;
    float m[4], ss[4], px[4], py[4];
#pragma unroll
    for (int i = 0; i < 4; i++) { m[i] = -1e30f; ss[i] = 0.f; px[i] = 0.f; py[i] = 0.f; }

    for (int t = 0; t < 64; ++t) {
        __syncthreads();
        for (int idx = tid; idx < 4096; idx += 256) {
            int c = idx >> 6, j = idx & 63;
            k_s[c][j] = f1b[c*HWC + t*64 + j];
        }
        __syncthreads();
        ull acc2[4][2];
#pragma unroll
        for (int i = 0; i < 4; i++) { acc2[i][0] = 0ull; acc2[i][1] = 0ull; }
#pragma unroll 8
        for (int c = 0; c < 64; ++c) {
            // k pairs: aligned float2 loads (row stride 66 floats, tk*4 offset -> 8B aligned)
            ull k01 = *(const ull*)&k_s[c][tk*4];
            ull k23 = *(const ull*)&k_s[c][tk*4+2];
#pragma unroll
            for (int i = 0; i < 4; i++) {
                float q = q_s[c][tq*4+i];
                ull qq = pk2(q, q);
                acc2[i][0] = fma2(qq, k01, acc2[i][0]);
                acc2[i][1] = fma2(qq, k23, acc2[i][1]);
            }
        }
#pragma unroll
        for (int i = 0; i < 4; i++) {
            float sc[4];
            unpk2(acc2[i][0], sc[0], sc[1]);
            unpk2(acc2[i][1], sc[2], sc[3]);
            float mt = m[i];
#pragma unroll
            for (int j = 0; j < 4; j++) mt = fmaxf(mt, sc[j]*0.125f);
            float f = __expf(m[i] - mt);
            float es = 0.f, ex = 0.f, ey = 0.f;
#pragma unroll
            for (int j = 0; j < 4; j++) {
                int jj = t*64 + tk*4 + j;
                float e  = __expf(sc[j]*0.125f - mt);
                float gx = (float)(2*(jj & 63) + 1) * (1.0f/64.0f) - 1.0f;
                float gy = (float)(2*(jj >> 6) + 1) * (1.0f/64.0f) - 1.0f;
                es += e; ex += e*gx; ey += e*gy;
            }
            ss[i] = ss[i]*f + es; px[i] = px[i]*f + ex; py[i] = py[i]*f + ey; m[i] = mt;
        }
    }
    __syncthreads();
    float* red = &k_s[0][0];   // reuse >= 4096 floats
#pragma unroll
    for (int i = 0; i < 4; i++) {
        int q = tq*4 + i;
        red[       q*16+tk] = m[i];
        red[1024 + q*16+tk] = ss[i];
        red[2048 + q*16+tk] = px[i];
        red[3072 + q*16+tk] = py[i];
    }
    __syncthreads();
    if (tid < 64) {
        int q = tid;
        float M = -1e30f;
        for (int t2 = 0; t2 < 16; t2++) M = fmaxf(M, red[q*16+t2]);
        float S = 0.f, X = 0.f, Y = 0.f;
        for (int t2 = 0; t2 < 16; t2++) {
            float f = __expf(red[q*16+t2] - M);
            S += red[1024 + q*16+t2]*f;
            X += red[2048 + q*16+t2]*f;
            Y += red[3072 + q*16+t2]*f;
        }
        int p = h*64 + q;
        g_cm0[(b*3+0)*HWC + p] = X / S;
        g_cm0[(b*3+1)*HWC + p] = Y / S;
        g_cm0[(b*3+2)*HWC + p] = 0.0f;
    }
}

// ---------------- bilinear grid-sample (zero padding via valid mask, matches reference) --
__global__ void gridsample_kernel(const float* __restrict__ img, const float* __restrict__ cm,
                                  float* __restrict__ out, int C, int H, int W) {
    int idx = blockIdx.x*256 + threadIdx.x;
    int HW = H*W;
    int total = B_*C*HW;
    if (idx >= total) return;
    int p = idx % HW; int c = (idx / HW) % C; int b = idx / (HW*C);
    float gx = cm[(b*3+0)*HW + p];
    float gy = cm[(b*3+1)*HW + p];
    float x = (gx + 1.0f)*(W*0.5f) - 0.5f;
    float y = (gy + 1.0f)*(H*0.5f) - 0.5f;
    float x0f = floorf(x), y0f = floorf(y);
    float wx = x - x0f, wy = y - y0f;
    int x0 = (int)x0f, y0 = (int)y0f;
    const float* im = img + (size_t)(b*C + c)*HW;
    float v[4];
#pragma unroll
    for (int iy = 0; iy < 2; iy++)
#pragma unroll
        for (int ix = 0; ix < 2; ix++) {
            int xi = x0 + ix, yi = y0 + iy;
            bool valid = (xi >= 0 && xi < W && yi >= 0 && yi < H);
            int xc = min(max(xi, 0), W-1), yc = min(max(yi, 0), H-1);
            v[iy*2+ix] = valid ? im[yc*W + xc] : 0.0f;
        }
    out[idx] = v[0]*(1-wx)*(1-wy) + v[1]*wx*(1-wy) + v[2]*(1-wx)*wy + v[3]*wx*wy;
}

// ---------------- channel concat builders ----------------
__global__ void concat_c_kernel(const float* __restrict__ f0c) {
    int idx = blockIdx.x*256 + threadIdx.x;
    if (idx >= B_*130*HWC) return;
    int p = idx % HWC; int c = (idx / HWC) % 130; int b = idx / (HWC*130);
    float v;
    if (c < 64)       v = f0c[(b*64 + c)*HWC + p];
    else if (c < 128) v = g_warped1c[(b*64 + (c-64))*HWC + p];
    else              v = g_cm0[(b*3 + (c-128))*HWC + p];
    g_xin[idx] = v;
}

__global__ void concat_f_kernel(const float* __restrict__ f0f) {
    int idx = blockIdx.x*256 + threadIdx.x;
    if (idx >= B_*50*HWF) return;
    int p = idx % HWF; int c = (idx / HWF) % 50; int b = idx / (HWF*50);
    float v;
    if (c < 24)      v = f0f[(b*24 + c)*HWF + p];
    else if (c < 48) v = g_warped1f[(b*24 + (c-24))*HWF + p];
    else             v = g_up[(b*3 + (c-48))*HWF + p];
    g_yin[idx] = v;
}

// ---------------- direct 3x3 conv, SAME, packed f32x2 ------------------------------------
// Block: 256 threads = 8 warps. Macro tile: 64 oc x 16x16 px.
// Warp w: oc [oc0 + 8w, +8). Lane l: row = l>>1, 8-px segment = (l&1)*8.
// Thread register tile: 4 oc-pairs (f32x2) x 8 px. Weights = natural float2 pairs from
// smem (broadcast LDS.64 across warp); input values duplicated {v,v} once, reused 4x.
// Input BN(scale,shift)+relu optionally fused on load.
__global__ __launch_bounds__(256, 2)
void conv3x3_kernel(const float* __restrict__ in, const float* __restrict__ wgt,
                    float* __restrict__ out,
                    int CIN, int COUT, int H, int W, int applyBn) {
    int b = blockIdx.z;
    int oc0 = blockIdx.y * 64;
    int tilesW = W >> 4;
    int th0 = (blockIdx.x / tilesW) * 16;
    int tw0 = (blockIdx.x % tilesW) * 16;
    int tid = threadIdx.x;
    int wrp = tid >> 5, ln = tid & 31;
    int hl = ln >> 1;
    int seg = (ln & 1) * 8;

    __shared__ __align__(16) float s_in[8][18][20];   // [ic][row 18][col 18 pad 20], halo 1
    __shared__ __align__(16) float s_w[8][9][64];     // [ic][tap][oc] (oc fastest)

    ull acc[4][8];
#pragma unroll
    for (int o2 = 0; o2 < 4; o2++)
#pragma unroll
        for (int j = 0; j < 8; j++) acc[o2][j] = 0ull;

    int nChunks = (CIN + 7) >> 3;
    for (int ch = 0; ch < nChunks; ++ch) {
        int ic0 = ch * 8;
        __syncthreads();
        // fill input tile: 8 ic x 18x18 (+BN/relu)
        for (int idx = tid; idx < 8*18*18; idx += 256) {
            int ic = idx / 324; int rem = idx % 324;
            int r = rem / 18, c = rem % 18;
            int gh = th0 + r - 1, gw = tw0 + c - 1;
            int icg = ic0 + ic;
            float v = 0.0f;
            if (icg < CIN && gh >= 0 && gh < H && gw >= 0 && gw < W) {
                v = in[((size_t)(b*CIN + icg)*H + gh)*W + gw];
                if (applyBn) v = fmaxf(fmaf(v, g_bnscale[icg], g_bnshift[icg]), 0.0f);
            }
            s_in[ic][r][c] = v;
        }
        // fill weights 8ic x 9tap x 64oc
        for (int idx = tid; idx < 8*9*64; idx += 256) {
            int ic = idx / 576; int k = (idx / 64) % 9; int oc = idx & 63;
            int icg = ic0 + ic;
            s_w[ic][k][oc] = (icg < CIN) ? wgt[((size_t)(oc0+oc)*CIN + icg)*9 + k] : 0.0f;
        }
        __syncthreads();

        for (int ic = 0; ic < 8; ++ic) {
#pragma unroll
            for (int kh = 0; kh < 3; ++kh) {
                const float* rp = &s_in[ic][hl + kh][seg];   // 16B aligned
                float4 a0 = *(const float4*)rp;
                float4 a1 = *(const float4*)(rp + 4);
                float v8 = rp[8], v9 = rp[9];
                ull vv[10];
                vv[0] = pk2(a0.x, a0.x); vv[1] = pk2(a0.y, a0.y);
                vv[2] = pk2(a0.z, a0.z); vv[3] = pk2(a0.w, a0.w);
                vv[4] = pk2(a1.x, a1.x); vv[5] = pk2(a1.y, a1.y);
                vv[6] = pk2(a1.z, a1.z); vv[7] = pk2(a1.w, a1.w);
                vv[8] = pk2(v8, v8);     vv[9] = pk2(v9, v9);
#pragma unroll
                for (int kw = 0; kw < 3; ++kw) {
                    const ull* wp = (const ull*)&s_w[ic][kh*3 + kw][wrp*8];
#pragma unroll
                    for (int o2 = 0; o2 < 4; ++o2) {
                        ull w2 = wp[o2];   // broadcast across warp
#pragma unroll
                        for (int j = 0; j < 8; ++j)
                            acc[o2][j] = fma2(w2, vv[kw + j], acc[o2][j]);
                    }
                }
            }
        }
    }
    // write out 8 oc x 8 px
    int orow = th0 + hl;
#pragma unroll
    for (int o2 = 0; o2 < 4; ++o2) {
        int oc = oc0 + wrp*8 + o2*2;
        float* p0 = &out[((size_t)(b*COUT + oc  )*H + orow)*W + tw0 + seg];
        float* p1 = &out[((size_t)(b*COUT + oc+1)*H + orow)*W + tw0 + seg];
#pragma unroll
        for (int j = 0; j < 8; ++j) {
            float lo, hi; unpk2(acc[o2][j], lo, hi);
            p0[j] = lo; p1[j] = hi;
        }
    }
}

// ---------------- per-channel batch stats -> scale/shift ----------------
__global__ void bnstats_kernel(const float* __restrict__ in, int C, int HW) {
    int c = blockIdx.x;
    int tid = threadIdx.x;
    float s = 0.f, s2 = 0.f;
    for (int b = 0; b < B_; ++b) {
        const float* p = in + (size_t)(b*C + c)*HW;
        for (int i = tid; i < HW; i += 256) { float v = p[i]; s += v; s2 += v*v; }
    }
    __shared__ float sh[256], sh2[256];
    sh[tid] = s; sh2[tid] = s2;
    __syncthreads();
    for (int o = 128; o > 0; o >>= 1) {
        if (tid < o) { sh[tid] += sh[tid+o]; sh2[tid] += sh2[tid+o]; }
        __syncthreads();
    }
    if (tid == 0) {
        float n = (float)(B_*HW);
        float mean = sh[0] / n;
        float var  = sh2[0] / n - mean*mean;
        float sc = rsqrtf(var + 1e-5f);
        g_bnscale[c] = sc;
        g_bnshift[c] = -mean * sc;
    }
}

// ---------------- 1x1 conv head: out = base + bias + W * relu(bn(in)) ----------------
__global__ void conv1x1_kernel(const float* __restrict__ inbuf, const float* __restrict__ wgt,
                               const float* __restrict__ bias, const float* __restrict__ base,
                               float* __restrict__ dout, float* __restrict__ dup,
                               int CIN, int HW) {
    __shared__ float s_w[3*256], s_sc[256], s_sh[256];
    int tid = threadIdx.x;
    for (int i = tid; i < 3*CIN; i += 256) s_w[i] = wgt[i];
    for (int i = tid; i < CIN; i += 256) { s_sc[i] = g_bnscale[i]; s_sh[i] = g_bnshift[i]; }
    __syncthreads();
    int idx = blockIdx.x*256 + tid;
    int p = idx % HW, b = idx / HW;
    float a0 = bias[0], a1 = bias[1], a2 = bias[2];
    const float* ip = inbuf + (size_t)b*CIN*HW + p;
    for (int ic = 0; ic < CIN; ++ic) {
        float v = ip[(size_t)ic*HW];
        v = fmaxf(fmaf(v, s_sc[ic], s_sh[ic]), 0.0f);
        a0 = fmaf(v, s_w[ic],        a0);
        a1 = fmaf(v, s_w[CIN+ic],    a1);
        a2 = fmaf(v, s_w[2*CIN+ic],  a2);
    }
    float r0 = base[(b*3+0)*HW + p] + a0;
    float r1 = base[(b*3+1)*HW + p] + a1;
    float r2 = base[(b*3+2)*HW + p] + a2;
    dout[(b*3+0)*HW + p] = r0;
    dout[(b*3+1)*HW + p] = r1;
    dout[(b*3+2)*HW + p] = r2;
    if (dup) {
        dup[(b*3+0)*HW + p] = r0;
        dup[(b*3+1)*HW + p] = r1;
        dup[(b*3+2)*HW + p] = r2;
    }
}

// ---------------- 2x bilinear upsample (half-pixel centers, edge clamp == jax renorm) ----
__global__ void upsample_kernel(const float* __restrict__ src3, float* __restrict__ dst3) {
    int idx = blockIdx.x*256 + threadIdx.x;
    if (idx >= B_*3*HWF) return;
    int p = idx % HWF; int c = (idx / HWF) % 3; int b = idx / (HWF*3);
    int wo = p & 127, ho = p >> 7;
    float sx = wo*0.5f - 0.25f, sy = ho*0.5f - 0.25f;
    float x0f = floorf(sx), y0f = floorf(sy);
    float wx = sx - x0f, wy = sy - y0f;
    int x0 = (int)x0f, y0 = (int)y0f;
    int x0c = min(max(x0, 0), 63),   x1c = min(max(x0+1, 0), 63);
    int y0c = min(max(y0, 0), 63),   y1c = min(max(y0+1, 0), 63);
    const float* s = src3 + (size_t)(b*3 + c)*HWC;
    float v = s[y0c*64+x0c]*(1-wx)*(1-wy) + s[y0c*64+x1c]*wx*(1-wy)
            + s[y1c*64+x0c]*(1-wx)*wy     + s[y1c*64+x1c]*wx*wy;
    dst3[idx] = v;
}

// ---------------- host driver (graph-capturable: kernel launches only) ----------------
extern "C" void kernel_launch(void* const* d_in, const int* in_sizes, int n_in,
                              void* d_out, int out_size) {
    const float* f0c = (const float*)d_in[0];
    const float* f1c = (const float*)d_in[1];
    const float* f0f = (const float*)d_in[2];
    const float* f1f = (const float*)d_in[3];
    const float* cw1 = (const float*)d_in[4];
    const float* cw2 = (const float*)d_in[5];
    const float* cw3 = (const float*)d_in[6];
    const float* cw4 = (const float*)d_in[7];
    const float* cw5 = (const float*)d_in[8];
    const float* cb5 = (const float*)d_in[9];
    const float* fw1 = (const float*)d_in[10];
    const float* fw2 = (const float*)d_in[11];
    const float* fw3 = (const float*)d_in[12];
    const float* fw4 = (const float*)d_in[13];
    const float* fw5 = (const float*)d_in[14];
    const float* fb5 = (const float*)d_in[15];

    float *p_cm0, *p_w1c, *p_xin, *p_c0, *p_c1, *p_cm, *p_up, *p_w1f, *p_yin, *p_f0, *p_f1;
    cudaGetSymbolAddress((void**)&p_cm0, g_cm0);
    cudaGetSymbolAddress((void**)&p_w1c, g_warped1c);
    cudaGetSymbolAddress((void**)&p_xin, g_xin);
    cudaGetSymbolAddress((void**)&p_c0,  g_cbuf0);
    cudaGetSymbolAddress((void**)&p_c1,  g_cbuf1);
    cudaGetSymbolAddress((void**)&p_cm,  g_cm);
    cudaGetSymbolAddress((void**)&p_up,  g_up);
    cudaGetSymbolAddress((void**)&p_w1f, g_warped1f);
    cudaGetSymbolAddress((void**)&p_yin, g_yin);
    cudaGetSymbolAddress((void**)&p_f0,  g_fbuf0);
    cudaGetSymbolAddress((void**)&p_f1,  g_fbuf1);

    // coarse path
    attention_kernel<<<dim3(64, B_), 256>>>(f0c, f1c);
    gridsample_kernel<<<(B_*64*HWC)/256, 256>>>(f1c, p_cm0, p_w1c, 64, 64, 64);
    concat_c_kernel<<<(B_*130*HWC + 255)/256, 256>>>(f0c);
    conv3x3_kernel<<<dim3(16, 4, B_), 256>>>(p_xin, cw1, p_c0, 130, 256, 64, 64, 0);
    bnstats_kernel<<<256, 256>>>(p_c0, 256, HWC);
    conv3x3_kernel<<<dim3(16, 4, B_), 256>>>(p_c0, cw2, p_c1, 256, 256, 64, 64, 1);
    bnstats_kernel<<<256, 256>>>(p_c1, 256, HWC);
    conv3x3_kernel<<<dim3(16, 4, B_), 256>>>(p_c1, cw3, p_c0, 256, 256, 64, 64, 1);
    bnstats_kernel<<<256, 256>>>(p_c0, 256, HWC);
    conv3x3_kernel<<<dim3(16, 4, B_), 256>>>(p_c0, cw4, p_c1, 256, 256, 64, 64, 1);
    bnstats_kernel<<<256, 256>>>(p_c1, 256, HWC);
    conv1x1_kernel<<<(B_*HWC)/256, 256>>>(p_c1, cw5, cb5, p_cm0, (float*)d_out, p_cm, 256, HWC);

    // fine path
    upsample_kernel<<<(B_*3*HWF)/256, 256>>>(p_cm, p_up);
    gridsample_kernel<<<(B_*24*HWF)/256, 256>>>(f1f, p_up, p_w1f, 24, 128, 128);
    concat_f_kernel<<<(B_*50*HWF + 255)/256, 256>>>(f0f);
    conv3x3_kernel<<<dim3(64, 1, B_), 256>>>(p_yin, fw1, p_f0, 50, 64, 128, 128, 0);
    bnstats_kernel<<<64, 256>>>(p_f0, 64, HWF);
    conv3x3_kernel<<<dim3(64, 1, B_), 256>>>(p_f0, fw2, p_f1, 64, 64, 128, 128, 1);
    bnstats_kernel<<<64, 256>>>(p_f1, 64, HWF);
    conv3x3_kernel<<<dim3(64, 1, B_), 256>>>(p_f1, fw3, p_f0, 64, 64, 128, 128, 1);
    bnstats_kernel<<<64, 256>>>(p_f0, 64, HWF);
    conv3x3_kernel<<<dim3(64, 1, B_), 256>>>(p_f0, fw4, p_f1, 64, 64, 128, 128, 1);
    bnstats_kernel<<<64, 256>>>(p_f1, 64, HWF);
    conv1x1_kernel<<<(B_*HWF)/256, 256>>>(p_f1, fw5, fb5, p_up,
                                          (float*)d_out + B_*3*HWC, (float*)0, 64, HWF);
}

// round 3
// speedup vs baseline: 1.5282x; 1.0028x over previous
#include <cuda_runtime.h>
#include <math.h>

#define B_  4
#define HWC 4096    // 64*64
#define HWF 16384   // 128*128

typedef unsigned long long ull;

__device__ __forceinline__ ull pk2(float a, float b) {
    ull r; asm("mov.b64 %0, {%1,%2};" : "=l"(r) : "f"(a), "f"(b)); return r;
}
__device__ __forceinline__ ull fma2(ull a, ull b, ull c) {
    ull d; asm("fma.rn.f32x2 %0, %1, %2, %3;" : "=l"(d) : "l"(a), "l"(b), "l"(c)); return d;
}
__device__ __forceinline__ void unpk2(ull v, float& lo, float& hi) {
    asm("mov.b64 {%0,%1}, %2;" : "=f"(lo), "=f"(hi) : "l"(v));
}

// ---------------- scratch (static device globals; no runtime allocation) ----------------
__device__ float g_cm0[B_*3*HWC];        // coarse_matches0 (warp x,y, 0)
__device__ float g_warped1c[B_*64*HWC];
__device__ float g_xin[B_*130*HWC];
__device__ float g_cbuf0[B_*256*HWC];
__device__ float g_cbuf1[B_*256*HWC];
__device__ float g_cm[B_*3*HWC];         // coarse_matches (final)
__device__ float g_up[B_*3*HWF];
__device__ float g_warped1f[B_*24*HWF];
__device__ float g_yin[B_*50*HWF];
__device__ float g_fbuf0[B_*64*HWF];
__device__ float g_fbuf1[B_*64*HWF];
__device__ float g_bnscale[256];
__device__ float g_bnshift[256];

// ---------------- fused correlation + softmax + expected-position ("attention") ----------
// block = (h row, batch). 64 queries/row, 4096 keys, D=64, V = analytic pos grid.
// 256 threads = 16 query-groups(4q) x 16 key-lanes(4k). QK inner product in packed f32x2.
__global__ void attention_kernel(const float* __restrict__ f0, const float* __restrict__ f1) {
    int b = blockIdx.y, h = blockIdx.x;
    int tid = threadIdx.x;
    __shared__ __align__(16) float q_s[64][66];
    __shared__ __align__(16) float k_s[64][66];
    const float* f0b = f0 + (size_t)b*64*HWC;
    const float* f1b = f1 + (size_t)b*64*HWC;
    for (int idx = tid; idx < 4096; idx += 256) {
        int c = idx >> 6, q = idx & 63;
        q_s[c][q] = f0b[c*HWC + h*64 + q];
    }
    int tq = tid >> 4, tk = tid & 15;
    float m[4], ss[4], px[4], py[4];
#pragma unroll
    for (int i = 0; i < 4; i++) { m[i] = -1e30f; ss[i] = 0.f; px[i] = 0.f; py[i] = 0.f; }

    for (int t = 0; t < 64; ++t) {
        __syncthreads();
        for (int idx = tid; idx < 4096; idx += 256) {
            int c = idx >> 6, j = idx & 63;
            k_s[c][j] = f1b[c*HWC + t*64 + j];
        }
        __syncthreads();
        ull acc2[4][2];
#pragma unroll
        for (int i = 0; i < 4; i++) { acc2[i][0] = 0ull; acc2[i][1] = 0ull; }
#pragma unroll 8
        for (int c = 0; c < 64; ++c) {
            // k pairs: aligned float2 loads (row stride 66 floats, tk*4 offset -> 8B aligned)
            ull k01 = *(const ull*)&k_s[c][tk*4];
            ull k23 = *(const ull*)&k_s[c][tk*4+2];
#pragma unroll
            for (int i = 0; i < 4; i++) {
                float q = q_s[c][tq*4+i];
                ull qq = pk2(q, q);
                acc2[i][0] = fma2(qq, k01, acc2[i][0]);
                acc2[i][1] = fma2(qq, k23, acc2[i][1]);
            }
        }
#pragma unroll
        for (int i = 0; i < 4; i++) {
            float sc[4];
            unpk2(acc2[i][0], sc[0], sc[1]);
            unpk2(acc2[i][1], sc[2], sc[3]);
            float mt = m[i];
#pragma unroll
            for (int j = 0; j < 4; j++) mt = fmaxf(mt, sc[j]*0.125f);
            float f = __expf(m[i] - mt);
            float es = 0.f, ex = 0.f, ey = 0.f;
#pragma unroll
            for (int j = 0; j < 4; j++) {
                int jj = t*64 + tk*4 + j;
                float e  = __expf(sc[j]*0.125f - mt);
                float gx = (float)(2*(jj & 63) + 1) * (1.0f/64.0f) - 1.0f;
                float gy = (float)(2*(jj >> 6) + 1) * (1.0f/64.0f) - 1.0f;
                es += e; ex += e*gx; ey += e*gy;
            }
            ss[i] = ss[i]*f + es; px[i] = px[i]*f + ex; py[i] = py[i]*f + ey; m[i] = mt;
        }
    }
    __syncthreads();
    float* red = &k_s[0][0];   // reuse >= 4096 floats
#pragma unroll
    for (int i = 0; i < 4; i++) {
        int q = tq*4 + i;
        red[       q*16+tk] = m[i];
        red[1024 + q*16+tk] = ss[i];
        red[2048 + q*16+tk] = px[i];
        red[3072 + q*16+tk] = py[i];
    }
    __syncthreads();
    if (tid < 64) {
        int q = tid;
        float M = -1e30f;
        for (int t2 = 0; t2 < 16; t2++) M = fmaxf(M, red[q*16+t2]);
        float S = 0.f, X = 0.f, Y = 0.f;
        for (int t2 = 0; t2 < 16; t2++) {
            float f = __expf(red[q*16+t2] - M);
            S += red[1024 + q*16+t2]*f;
            X += red[2048 + q*16+t2]*f;
            Y += red[3072 + q*16+t2]*f;
        }
        int p = h*64 + q;
        g_cm0[(b*3+0)*HWC + p] = X / S;
        g_cm0[(b*3+1)*HWC + p] = Y / S;
        g_cm0[(b*3+2)*HWC + p] = 0.0f;
    }
}

// ---------------- bilinear grid-sample (zero padding via valid mask, matches reference) --
__global__ void gridsample_kernel(const float* __restrict__ img, const float* __restrict__ cm,
                                  float* __restrict__ out, int C, int H, int W) {
    int idx = blockIdx.x*256 + threadIdx.x;
    int HW = H*W;
    int total = B_*C*HW;
    if (idx >= total) return;
    int p = idx % HW; int c = (idx / HW) % C; int b = idx / (HW*C);
    float gx = cm[(b*3+0)*HW + p];
    float gy = cm[(b*3+1)*HW + p];
    float x = (gx + 1.0f)*(W*0.5f) - 0.5f;
    float y = (gy + 1.0f)*(H*0.5f) - 0.5f;
    float x0f = floorf(x), y0f = floorf(y);
    float wx = x - x0f, wy = y - y0f;
    int x0 = (int)x0f, y0 = (int)y0f;
    const float* im = img + (size_t)(b*C + c)*HW;
    float v[4];
#pragma unroll
    for (int iy = 0; iy < 2; iy++)
#pragma unroll
        for (int ix = 0; ix < 2; ix++) {
            int xi = x0 + ix, yi = y0 + iy;
            bool valid = (xi >= 0 && xi < W && yi >= 0 && yi < H);
            int xc = min(max(xi, 0), W-1), yc = min(max(yi, 0), H-1);
            v[iy*2+ix] = valid ? im[yc*W + xc] : 0.0f;
        }
    out[idx] = v[0]*(1-wx)*(1-wy) + v[1]*wx*(1-wy) + v[2]*(1-wx)*wy + v[3]*wx*wy;
}

// ---------------- channel concat builders ----------------
__global__ void concat_c_kernel(const float* __restrict__ f0c) {
    int idx = blockIdx.x*256 + threadIdx.x;
    if (idx >= B_*130*HWC) return;
    int p = idx % HWC; int c = (idx / HWC) % 130; int b = idx / (HWC*130);
    float v;
    if (c < 64)       v = f0c[(b*64 + c)*HWC + p];
    else if (c < 128) v = g_warped1c[(b*64 + (c-64))*HWC + p];
    else              v = g_cm0[(b*3 + (c-128))*HWC + p];
    g_xin[idx] = v;
}

__global__ void concat_f_kernel(const float* __restrict__ f0f) {
    int idx = blockIdx.x*256 + threadIdx.x;
    if (idx >= B_*50*HWF) return;
    int p = idx % HWF; int c = (idx / HWF) % 50; int b = idx / (HWF*50);
    float v;
    if (c < 24)      v = f0f[(b*24 + c)*HWF + p];
    else if (c < 48) v = g_warped1f[(b*24 + (c-24))*HWF + p];
    else             v = g_up[(b*3 + (c-48))*HWF + p];
    g_yin[idx] = v;
}

// ---------------- direct 3x3 conv, SAME, packed f32x2 ------------------------------------
// Block: 256 threads = 8 warps. Macro tile: 64 oc x 16x16 px.
// Warp w: oc [oc0 + 8w, +8). Lane l: row = l>>1, 8-px segment = (l&1)*8.
// Thread register tile: 4 oc-pairs (f32x2) x 8 px. Weights = natural float2 pairs from
// smem (broadcast LDS.64 across warp); input values duplicated {v,v} once, reused 4x.
// Input BN(scale,shift)+relu optionally fused on load.
__global__ __launch_bounds__(256, 2)
void conv3x3_kernel(const float* __restrict__ in, const float* __restrict__ wgt,
                    float* __restrict__ out,
                    int CIN, int COUT, int H, int W, int applyBn) {
    int b = blockIdx.z;
    int oc0 = blockIdx.y * 64;
    int tilesW = W >> 4;
    int th0 = (blockIdx.x / tilesW) * 16;
    int tw0 = (blockIdx.x % tilesW) * 16;
    int tid = threadIdx.x;
    int wrp = tid >> 5, ln = tid & 31;
    int hl = ln >> 1;
    int seg = (ln & 1) * 8;

    __shared__ __align__(16) float s_in[8][18][20];   // [ic][row 18][col 18 pad 20], halo 1
    __shared__ __align__(16) float s_w[8][9][64];     // [ic][tap][oc] (oc fastest)

    ull acc[4][8];
#pragma unroll
    for (int o2 = 0; o2 < 4; o2++)
#pragma unroll
        for (int j = 0; j < 8; j++) acc[o2][j] = 0ull;

    int nChunks = (CIN + 7) >> 3;
    for (int ch = 0; ch < nChunks; ++ch) {
        int ic0 = ch * 8;
        __syncthreads();
        // fill input tile: 8 ic x 18x18 (+BN/relu)
        for (int idx = tid; idx < 8*18*18; idx += 256) {
            int ic = idx / 324; int rem = idx % 324;
            int r = rem / 18, c = rem % 18;
            int gh = th0 + r - 1, gw = tw0 + c - 1;
            int icg = ic0 + ic;
            float v = 0.0f;
            if (icg < CIN && gh >= 0 && gh < H && gw >= 0 && gw < W) {
                v = in[((size_t)(b*CIN + icg)*H + gh)*W + gw];
                if (applyBn) v = fmaxf(fmaf(v, g_bnscale[icg], g_bnshift[icg]), 0.0f);
            }
            s_in[ic][r][c] = v;
        }
        // fill weights 8ic x 9tap x 64oc
        for (int idx = tid; idx < 8*9*64; idx += 256) {
            int ic = idx / 576; int k = (idx / 64) % 9; int oc = idx & 63;
            int icg = ic0 + ic;
            s_w[ic][k][oc] = (icg < CIN) ? wgt[((size_t)(oc0+oc)*CIN + icg)*9 + k] : 0.0f;
        }
        __syncthreads();

        for (int ic = 0; ic < 8; ++ic) {
#pragma unroll
            for (int kh = 0; kh < 3; ++kh) {
                const float* rp = &s_in[ic][hl + kh][seg];   // 16B aligned
                float4 a0 = *(const float4*)rp;
                float4 a1 = *(const float4*)(rp + 4);
                float v8 = rp[8], v9 = rp[9];
                ull vv[10];
                vv[0] = pk2(a0.x, a0.x); vv[1] = pk2(a0.y, a0.y);
                vv[2] = pk2(a0.z, a0.z); vv[3] = pk2(a0.w, a0.w);
                vv[4] = pk2(a1.x, a1.x); vv[5] = pk2(a1.y, a1.y);
                vv[6] = pk2(a1.z, a1.z); vv[7] = pk2(a1.w, a1.w);
                vv[8] = pk2(v8, v8);     vv[9] = pk2(v9, v9);
#pragma unroll
                for (int kw = 0; kw < 3; ++kw) {
                    const ull* wp = (const ull*)&s_w[ic][kh*3 + kw][wrp*8];
#pragma unroll
                    for (int o2 = 0; o2 < 4; ++o2) {
                        ull w2 = wp[o2];   // broadcast across warp
#pragma unroll
                        for (int j = 0; j < 8; ++j)
                            acc[o2][j] = fma2(w2, vv[kw + j], acc[o2][j]);
                    }
                }
            }
        }
    }
    // write out 8 oc x 8 px
    int orow = th0 + hl;
#pragma unroll
    for (int o2 = 0; o2 < 4; ++o2) {
        int oc = oc0 + wrp*8 + o2*2;
        float* p0 = &out[((size_t)(b*COUT + oc  )*H + orow)*W + tw0 + seg];
        float* p1 = &out[((size_t)(b*COUT + oc+1)*H + orow)*W + tw0 + seg];
#pragma unroll
        for (int j = 0; j < 8; ++j) {
            float lo, hi; unpk2(acc[o2][j], lo, hi);
            p0[j] = lo; p1[j] = hi;
        }
    }
}

// ---------------- per-channel batch stats -> scale/shift ----------------
__global__ void bnstats_kernel(const float* __restrict__ in, int C, int HW) {
    int c = blockIdx.x;
    int tid = threadIdx.x;
    float s = 0.f, s2 = 0.f;
    for (int b = 0; b < B_; ++b) {
        const float* p = in + (size_t)(b*C + c)*HW;
        for (int i = tid; i < HW; i += 256) { float v = p[i]; s += v; s2 += v*v; }
    }
    __shared__ float sh[256], sh2[256];
    sh[tid] = s; sh2[tid] = s2;
    __syncthreads();
    for (int o = 128; o > 0; o >>= 1) {
        if (tid < o) { sh[tid] += sh[tid+o]; sh2[tid] += sh2[tid+o]; }
        __syncthreads();
    }
    if (tid == 0) {
        float n = (float)(B_*HW);
        float mean = sh[0] / n;
        float var  = sh2[0] / n - mean*mean;
        float sc = rsqrtf(var + 1e-5f);
        g_bnscale[c] = sc;
        g_bnshift[c] = -mean * sc;
    }
}

// ---------------- 1x1 conv head: out = base + bias + W * relu(bn(in)) ----------------
__global__ void conv1x1_kernel(const float* __restrict__ inbuf, const float* __restrict__ wgt,
                               const float* __restrict__ bias, const float* __restrict__ base,
                               float* __restrict__ dout, float* __restrict__ dup,
                               int CIN, int HW) {
    __shared__ float s_w[3*256], s_sc[256], s_sh[256];
    int tid = threadIdx.x;
    for (int i = tid; i < 3*CIN; i += 256) s_w[i] = wgt[i];
    for (int i = tid; i < CIN; i += 256) { s_sc[i] = g_bnscale[i]; s_sh[i] = g_bnshift[i]; }
    __syncthreads();
    int idx = blockIdx.x*256 + tid;
    int p = idx % HW, b = idx / HW;
    float a0 = bias[0], a1 = bias[1], a2 = bias[2];
    const float* ip = inbuf + (size_t)b*CIN*HW + p;
    for (int ic = 0; ic < CIN; ++ic) {
        float v = ip[(size_t)ic*HW];
        v = fmaxf(fmaf(v, s_sc[ic], s_sh[ic]), 0.0f);
        a0 = fmaf(v, s_w[ic],        a0);
        a1 = fmaf(v, s_w[CIN+ic],    a1);
        a2 = fmaf(v, s_w[2*CIN+ic],  a2);
    }
    float r0 = base[(b*3+0)*HW + p] + a0;
    float r1 = base[(b*3+1)*HW + p] + a1;
    float r2 = base[(b*3+2)*HW + p] + a2;
    dout[(b*3+0)*HW + p] = r0;
    dout[(b*3+1)*HW + p] = r1;
    dout[(b*3+2)*HW + p] = r2;
    if (dup) {
        dup[(b*3+0)*HW + p] = r0;
        dup[(b*3+1)*HW + p] = r1;
        dup[(b*3+2)*HW + p] = r2;
    }
}

// ---------------- 2x bilinear upsample (half-pixel centers, edge clamp == jax renorm) ----
__global__ void upsample_kernel(const float* __restrict__ src3, float* __restrict__ dst3) {
    int idx = blockIdx.x*256 + threadIdx.x;
    if (idx >= B_*3*HWF) return;
    int p = idx % HWF; int c = (idx / HWF) % 3; int b = idx / (HWF*3);
    int wo = p & 127, ho = p >> 7;
    float sx = wo*0.5f - 0.25f, sy = ho*0.5f - 0.25f;
    float x0f = floorf(sx), y0f = floorf(sy);
    float wx = sx - x0f, wy = sy - y0f;
    int x0 = (int)x0f, y0 = (int)y0f;
    int x0c = min(max(x0, 0), 63),   x1c = min(max(x0+1, 0), 63);
    int y0c = min(max(y0, 0), 63),   y1c = min(max(y0+1, 0), 63);
    const float* s = src3 + (size_t)(b*3 + c)*HWC;
    float v = s[y0c*64+x0c]*(1-wx)*(1-wy) + s[y0c*64+x1c]*wx*(1-wy)
            + s[y1c*64+x0c]*(1-wx)*wy     + s[y1c*64+x1c]*wx*wy;
    dst3[idx] = v;
}

// ---------------- host driver (graph-capturable: kernel launches only) ----------------
extern "C" void kernel_launch(void* const* d_in, const int* in_sizes, int n_in,
                              void* d_out, int out_size) {
    const float* f0c = (const float*)d_in[0];
    const float* f1c = (const float*)d_in[1];
    const float* f0f = (const float*)d_in[2];
    const float* f1f = (const float*)d_in[3];
    const float* cw1 = (const float*)d_in[4];
    const float* cw2 = (const float*)d_in[5];
    const float* cw3 = (const float*)d_in[6];
    const float* cw4 = (const float*)d_in[7];
    const float* cw5 = (const float*)d_in[8];
    const float* cb5 = (const float*)d_in[9];
    const float* fw1 = (const float*)d_in[10];
    const float* fw2 = (const float*)d_in[11];
    const float* fw3 = (const float*)d_in[12];
    const float* fw4 = (const float*)d_in[13];
    const float* fw5 = (const float*)d_in[14];
    const float* fb5 = (const float*)d_in[15];

    float *p_cm0, *p_w1c, *p_xin, *p_c0, *p_c1, *p_cm, *p_up, *p_w1f, *p_yin, *p_f0, *p_f1;
    cudaGetSymbolAddress((void**)&p_cm0, g_cm0);
    cudaGetSymbolAddress((void**)&p_w1c, g_warped1c);
    cudaGetSymbolAddress((void**)&p_xin, g_xin);
    cudaGetSymbolAddress((void**)&p_c0,  g_cbuf0);
    cudaGetSymbolAddress((void**)&p_c1,  g_cbuf1);
    cudaGetSymbolAddress((void**)&p_cm,  g_cm);
    cudaGetSymbolAddress((void**)&p_up,  g_up);
    cudaGetSymbolAddress((void**)&p_w1f, g_warped1f);
    cudaGetSymbolAddress((void**)&p_yin, g_yin);
    cudaGetSymbolAddress((void**)&p_f0,  g_fbuf0);
    cudaGetSymbolAddress((void**)&p_f1,  g_fbuf1);

    // coarse path
    attention_kernel<<<dim3(64, B_), 256>>>(f0c, f1c);
    gridsample_kernel<<<(B_*64*HWC)/256, 256>>>(f1c, p_cm0, p_w1c, 64, 64, 64);
    concat_c_kernel<<<(B_*130*HWC + 255)/256, 256>>>(f0c);
    conv3x3_kernel<<<dim3(16, 4, B_), 256>>>(p_xin, cw1, p_c0, 130, 256, 64, 64, 0);
    bnstats_kernel<<<256, 256>>>(p_c0, 256, HWC);
    conv3x3_kernel<<<dim3(16, 4, B_), 256>>>(p_c0, cw2, p_c1, 256, 256, 64, 64, 1);
    bnstats_kernel<<<256, 256>>>(p_c1, 256, HWC);
    conv3x3_kernel<<<dim3(16, 4, B_), 256>>>(p_c1, cw3, p_c0, 256, 256, 64, 64, 1);
    bnstats_kernel<<<256, 256>>>(p_c0, 256, HWC);
    conv3x3_kernel<<<dim3(16, 4, B_), 256>>>(p_c0, cw4, p_c1, 256, 256, 64, 64, 1);
    bnstats_kernel<<<256, 256>>>(p_c1, 256, HWC);
    conv1x1_kernel<<<(B_*HWC)/256, 256>>>(p_c1, cw5, cb5, p_cm0, (float*)d_out, p_cm, 256, HWC);

    // fine path
    upsample_kernel<<<(B_*3*HWF)/256, 256>>>(p_cm, p_up);
    gridsample_kernel<<<(B_*24*HWF)/256, 256>>>(f1f, p_up, p_w1f, 24, 128, 128);
    concat_f_kernel<<<(B_*50*HWF + 255)/256, 256>>>(f0f);
    conv3x3_kernel<<<dim3(64, 1, B_), 256>>>(p_yin, fw1, p_f0, 50, 64, 128, 128, 0);
    bnstats_kernel<<<64, 256>>>(p_f0, 64, HWF);
    conv3x3_kernel<<<dim3(64, 1, B_), 256>>>(p_f0, fw2, p_f1, 64, 64, 128, 128, 1);
    bnstats_kernel<<<64, 256>>>(p_f1, 64, HWF);
    conv3x3_kernel<<<dim3(64, 1, B_), 256>>>(p_f1, fw3, p_f0, 64, 64, 128, 128, 1);
    bnstats_kernel<<<64, 256>>>(p_f0, 64, HWF);
    conv3x3_kernel<<<dim3(64, 1, B_), 256>>>(p_f0, fw4, p_f1, 64, 64, 128, 128, 1);
    bnstats_kernel<<<64, 256>>>(p_f1, 64, HWF);
    conv1x1_kernel<<<(B_*HWF)/256, 256>>>(p_f1, fw5, fb5, p_up,
                                          (float*)d_out + B_*3*HWC, (float*)0, 64, HWF);
}